// round 7
// baseline (speedup 1.0000x reference)
#include <cuda_runtime.h>
#include <cstdint>
#include <cstring>

#define T_STEPS 2048
#define BATCH   8
#define DIMK    1024
#define NST     64
#define M_ROWS  (T_STEPS * BATCH)
#define NCOL    256

#define NMB       128     // proj m-blocks (16 timesteps each)
#define SCAN_CTAS 128
#define PROJ_CTAS (NMB * 4)

// 16 MB scratch: projections, layout [t*BATCH+b][ k(0:64) | q(64:128) | v(128:192) | alpha(192:256) ]
__device__ __align__(16) float g_proj[(size_t)M_ROWS * NCOL];
__device__ int g_flags[NMB];   // ==4 when mblock's 4 projections complete

union F2U { float2 f2; unsigned long long u; };

__device__ __forceinline__ float2 f2fma(float2 a, float2 b, float2 c) {
    F2U ua, ub, uc, ud; ua.f2 = a; ub.f2 = b; uc.f2 = c;
    asm("fma.rn.f32x2 %0, %1, %2, %3;" : "=l"(ud.u) : "l"(ua.u), "l"(ub.u), "l"(uc.u));
    return ud.f2;
}
__device__ __forceinline__ float2 f2mul(float2 a, float2 b) {
    F2U ua, ub, ud; ua.f2 = a; ub.f2 = b;
    asm("mul.rn.f32x2 %0, %1, %2;" : "=l"(ud.u) : "l"(ua.u), "l"(ub.u));
    return ud.f2;
}
__device__ __forceinline__ float2 f2add(float2 a, float2 b) {
    F2U ua, ub, ud; ua.f2 = a; ub.f2 = b;
    asm("add.rn.f32x2 %0, %1, %2;" : "=l"(ud.u) : "l"(ua.u), "l"(ub.u));
    return ud.f2;
}
__device__ __forceinline__ float2 f2dup(float a) {
    F2U ud;
    asm("mov.b64 %0, {%1, %1};" : "=l"(ud.u) : "f"(a));
    return ud.f2;
}
__device__ __forceinline__ float sigmoidf_fast(float x) {
    return __fdividef(1.0f, 1.0f + __expf(-x));
}

// ============================================================================
// shared memory: union of proj (25600 B) and scan (8192 B) layouts
// ============================================================================
#define BM 128
#define BN 64
#define BK 16
#define ASTRIDE (BM + 4)
#define BSTRIDE (BN + 4)
#define PROJ_SMEM_FLOATS (2 * BK * ASTRIDE + 2 * BK * BSTRIDE)   // 6400
#define DPF 8

// ============================================================================
// proj role: one 128-row m-block x one weight matrix per CTA (R6 inner loop)
// ============================================================================
__device__ void proj_role(
    float* smem,
    int pb,                               // 0..511
    const float* __restrict__ x,
    const float* __restrict__ Wk, const float* __restrict__ Wq,
    const float* __restrict__ Wv, const float* __restrict__ Wa,
    const float* __restrict__ b_alpha)
{
    float* As = smem;                         // [2][BK][ASTRIDE]
    float* Bs = smem + 2 * BK * ASTRIDE;      // [2][BK][BSTRIDE]

    const int tid    = threadIdx.x;
    const int mblock = pb >> 2;
    const int sel    = pb & 3;
    const int m0     = mblock * BM;
    const float* W = (sel == 0) ? Wk : (sel == 1) ? Wq : (sel == 2) ? Wv : Wa;

    const int warp  = tid >> 5;
    const int lane  = tid & 31;
    const int wm    = warp >> 1;
    const int wn    = warp & 1;
    const int lane_m = lane & 7;
    const int lane_n = lane >> 3;
    const int arow  = wm * 64 + lane_m * 4;
    const int bcol  = wn * 32 + lane_n * 8;

    const int xrow = tid >> 2;
    const int xcol = (tid & 3) * 4;
    const int wrow = tid >> 1;
    const int wcol = (tid & 1) * 8;

    const float* xp = &x[(size_t)(m0 + xrow) * DIMK + xcol];
    const float* wp = &W[(size_t)wrow * DIMK + wcol];

    float4 xr[4], wr[2];
    #pragma unroll
    for (int j = 0; j < 4; j++)
        xr[j] = *reinterpret_cast<const float4*>(xp + (size_t)j * 32 * DIMK);
    wr[0] = *reinterpret_cast<const float4*>(wp);
    wr[1] = *reinterpret_cast<const float4*>(wp + 4);

    float2 acc[4][8];
    #pragma unroll
    for (int ip = 0; ip < 4; ip++)
        #pragma unroll
        for (int j = 0; j < 8; j++) acc[ip][j] = make_float2(0.f, 0.f);

    int p = 0;
    for (int k0 = 0; k0 < DIMK; k0 += BK) {
        float* Ap = As + p * BK * ASTRIDE;
        float* Bp = Bs + p * BK * BSTRIDE;
        #pragma unroll
        for (int j = 0; j < 4; j++) {
            const int r = xrow + j * 32;
            Ap[(xcol + 0) * ASTRIDE + r] = xr[j].x;
            Ap[(xcol + 1) * ASTRIDE + r] = xr[j].y;
            Ap[(xcol + 2) * ASTRIDE + r] = xr[j].z;
            Ap[(xcol + 3) * ASTRIDE + r] = xr[j].w;
        }
        Bp[(wcol + 0) * BSTRIDE + wrow] = wr[0].x;
        Bp[(wcol + 1) * BSTRIDE + wrow] = wr[0].y;
        Bp[(wcol + 2) * BSTRIDE + wrow] = wr[0].z;
        Bp[(wcol + 3) * BSTRIDE + wrow] = wr[0].w;
        Bp[(wcol + 4) * BSTRIDE + wrow] = wr[1].x;
        Bp[(wcol + 5) * BSTRIDE + wrow] = wr[1].y;
        Bp[(wcol + 6) * BSTRIDE + wrow] = wr[1].z;
        Bp[(wcol + 7) * BSTRIDE + wrow] = wr[1].w;
        __syncthreads();

        if (k0 + BK < DIMK) {
            #pragma unroll
            for (int j = 0; j < 4; j++)
                xr[j] = *reinterpret_cast<const float4*>(xp + (size_t)j * 32 * DIMK + k0 + BK);
            wr[0] = *reinterpret_cast<const float4*>(wp + k0 + BK);
            wr[1] = *reinterpret_cast<const float4*>(wp + k0 + BK + 4);
        }

        #pragma unroll
        for (int k = 0; k < BK; k++) {
            float4 a0 = *reinterpret_cast<const float4*>(&Ap[k * ASTRIDE + arow]);
            float4 a1 = *reinterpret_cast<const float4*>(&Ap[k * ASTRIDE + arow + 32]);
            float2 am[4] = { make_float2(a0.x, a0.y), make_float2(a0.z, a0.w),
                             make_float2(a1.x, a1.y), make_float2(a1.z, a1.w) };
            {
                float4 b0 = *reinterpret_cast<const float4*>(&Bp[k * BSTRIDE + bcol]);
                float2 bd[4] = { f2dup(b0.x), f2dup(b0.y), f2dup(b0.z), f2dup(b0.w) };
                #pragma unroll
                for (int ip = 0; ip < 4; ip++)
                    #pragma unroll
                    for (int j = 0; j < 4; j++)
                        acc[ip][j] = f2fma(am[ip], bd[j], acc[ip][j]);
            }
            {
                float4 b1 = *reinterpret_cast<const float4*>(&Bp[k * BSTRIDE + bcol + 4]);
                float2 bd[4] = { f2dup(b1.x), f2dup(b1.y), f2dup(b1.z), f2dup(b1.w) };
                #pragma unroll
                for (int ip = 0; ip < 4; ip++)
                    #pragma unroll
                    for (int j = 0; j < 4; j++)
                        acc[ip][j + 4] = f2fma(am[ip], bd[j], acc[ip][j + 4]);
            }
        }
        p ^= 1;
        __syncthreads();
    }

    #pragma unroll
    for (int ip = 0; ip < 4; ip++) {
        #pragma unroll
        for (int h = 0; h < 2; h++) {
            const int row = m0 + arow + (ip >> 1) * 32 + (ip & 1) * 2 + h;
            float o[8];
            #pragma unroll
            for (int j = 0; j < 8; j++)
                o[j] = h ? acc[ip][j].y : acc[ip][j].x;
            if (sel == 3) {
                #pragma unroll
                for (int j = 0; j < 8; j++)
                    o[j] = sigmoidf_fast(o[j] + b_alpha[bcol + j]);
            }
            float* dst = &g_proj[(size_t)row * NCOL + sel * 64 + bcol];
            *reinterpret_cast<float4*>(dst)     = make_float4(o[0], o[1], o[2], o[3]);
            *reinterpret_cast<float4*>(dst + 4) = make_float4(o[4], o[5], o[6], o[7]);
        }
    }

    // signal completion of this (mblock, sel)
    __threadfence();
    __syncthreads();
    if (tid == 0)
        atomicAdd(&g_flags[mblock], 1);
}

// ============================================================================
// scan role (R5 loop) + flag polling once per 16-step group
// ============================================================================
struct ScanCtx {
    const float* gp_base;
    float* out;
    uint32_t sbase;
    int b, i, c, loff;
    float dgl, bgl;
};

__device__ __forceinline__ void wait_flag(int mb) {
    if (mb > NMB - 1) mb = NMB - 1;
    int* f = &g_flags[mb];
    int v;
    while (true) {
        asm volatile("ld.acquire.gpu.global.b32 %0, [%1];" : "=r"(v) : "l"(f));
        if (v >= 4) break;
        __nanosleep(64);
    }
}

__device__ __forceinline__ void scan_step(
    const ScanCtx& ctx, int t,
    float2 (&s)[4],
    float2 (&kc)[4], float2 (&kn)[4],
    float2 (&qp)[4], float2 (&qc)[4],
    float v_c, float a_c,
    float& v_n, float& a_n,
    float& r,
    float* buf)
{
    {
        int tf = t + DPF - 1;
        if (tf > T_STEPS - 1) tf = T_STEPS - 1;
        int slot = tf & (DPF - 1);
        const float* src = ctx.gp_base + (size_t)tf * BATCH * NCOL + ctx.loff;
        uint32_t sa = ctx.sbase + (uint32_t)(slot * NCOL + ctx.loff) * 4u;
        asm volatile(
            "cp.async.ca.shared.global [%0], [%1], 16;\n\t"
            "cp.async.ca.shared.global [%2], [%3], 16;\n\t"
            :: "r"(sa), "l"(src), "r"(sa + 16u), "l"(src + 4));
        asm volatile("cp.async.commit_group;");
    }
    asm volatile("cp.async.wait_group %0;" :: "n"(DPF - 2));
    __syncwarp();

    const int tn = (t + 1 < T_STEPS) ? (t + 1) : t;
    const float* pn = buf + (size_t)(tn & (DPF - 1)) * NCOL;
    const float* pc = buf + (size_t)(t & (DPF - 1)) * NCOL;
    {
        float4 kv0 = *reinterpret_cast<const float4*>(pn + ctx.c * 8);
        float4 kv1 = *reinterpret_cast<const float4*>(pn + ctx.c * 8 + 4);
        kn[0] = make_float2(kv0.x, kv0.y); kn[1] = make_float2(kv0.z, kv0.w);
        kn[2] = make_float2(kv1.x, kv1.y); kn[3] = make_float2(kv1.z, kv1.w);
        float4 qv0 = *reinterpret_cast<const float4*>(pc + 64 + ctx.c * 8);
        float4 qv1 = *reinterpret_cast<const float4*>(pc + 64 + ctx.c * 8 + 4);
        qc[0] = make_float2(qv0.x, qv0.y); qc[1] = make_float2(qv0.z, qv0.w);
        qc[2] = make_float2(qv1.x, qv1.y); qc[3] = make_float2(qv1.z, qv1.w);
        v_n = pn[128 + ctx.i];
        a_n = pn[192 + ctx.i];
    }

    float2 xa = f2mul(s[0], kn[0]);
    float2 xb = f2mul(s[1], kn[1]);
    float2 oa = f2mul(s[0], qp[0]);
    float2 ob = f2mul(s[1], qp[1]);
    float2 da = f2mul(kc[0], kn[0]);
    float2 db = f2mul(kc[1], kn[1]);
    xa = f2fma(s[2], kn[2], xa);
    xb = f2fma(s[3], kn[3], xb);
    oa = f2fma(s[2], qp[2], oa);
    ob = f2fma(s[3], qp[3], ob);
    da = f2fma(kc[2], kn[2], da);
    db = f2fma(kc[3], kn[3], db);
    xa = f2add(xa, xb);
    oa = f2add(oa, ob);
    da = f2add(da, db);
    float a1 = xa.x + xa.y;
    float oq = oa.x + oa.y;
    float d2 = da.x + da.y;

    a1 += __shfl_xor_sync(0xffffffffu, a1, 1);
    oq += __shfl_xor_sync(0xffffffffu, oq, 1);
    d2 += __shfl_xor_sync(0xffffffffu, d2, 1);
    a1 += __shfl_xor_sync(0xffffffffu, a1, 2);
    oq += __shfl_xor_sync(0xffffffffu, oq, 2);
    d2 += __shfl_xor_sync(0xffffffffu, d2, 2);
    a1 += __shfl_xor_sync(0xffffffffu, a1, 4);
    oq += __shfl_xor_sync(0xffffffffu, oq, 4);
    d2 += __shfl_xor_sync(0xffffffffu, d2, 4);

    float e;
    asm("ex2.approx.f32 %0, %1;" : "=f"(e) : "f"(__fmaf_rn(ctx.dgl, r, ctx.bgl)));
    float gt;
    asm("rcp.approx.f32 %0, %1;" : "=f"(gt) : "f"(1.0f + e));
    const float beta = (1.0f - a_c) * v_c * gt;

    const float2 av = f2dup(a_c);
    const float2 bv = f2dup(beta);
    #pragma unroll
    for (int m = 0; m < 4; m++)
        s[m] = f2fma(av, s[m], f2mul(bv, kc[m]));

    r = __fmaf_rn(a_c, a1, beta * d2);

    if (t > 0 && ctx.c == 0)
        ctx.out[((size_t)(t - 1) * BATCH + ctx.b) * NST + ctx.i] = oq;
}

__device__ void scan_role(
    float* smem,
    int bx,
    const float* __restrict__ S0,
    const float* __restrict__ d_g,
    const float* __restrict__ b_g,
    float* __restrict__ out,
    float* __restrict__ Sfin)
{
    float* buf = smem;   // [DPF][NCOL]

    const int b    = bx >> 4;
    const int rg   = bx & 15;
    const int lane = threadIdx.x;
    const int r_   = lane >> 3;
    const int c    = lane & 7;
    const int i    = rg * 4 + r_;

    const float L2E = 1.4426950408889634f;

    ScanCtx ctx;
    ctx.gp_base = &g_proj[(size_t)b * NCOL];
    ctx.out  = out;
    ctx.b = b; ctx.i = i; ctx.c = c;
    ctx.loff = lane * 8;
    ctx.dgl = -d_g[i] * L2E;
    ctx.bgl = -b_g[i] * L2E;
    ctx.sbase = (uint32_t)__cvta_generic_to_shared(buf);

    float2 s[4];
    {
        const float4* sp = reinterpret_cast<const float4*>(&S0[(size_t)(b * NST + i) * NST + c * 8]);
        float4 v0 = sp[0], v1 = sp[1];
        s[0] = make_float2(v0.x, v0.y); s[1] = make_float2(v0.z, v0.w);
        s[2] = make_float2(v1.x, v1.y); s[3] = make_float2(v1.z, v1.w);
    }

    // wait for timesteps 0..15 before the prologue prefetch of steps 0..6
    wait_flag(0);

    #pragma unroll
    for (int d = 0; d < DPF - 1; d++) {
        const float* src = ctx.gp_base + (size_t)d * BATCH * NCOL + ctx.loff;
        uint32_t sa = ctx.sbase + (uint32_t)(d * NCOL + ctx.loff) * 4u;
        asm volatile(
            "cp.async.ca.shared.global [%0], [%1], 16;\n\t"
            "cp.async.ca.shared.global [%2], [%3], 16;\n\t"
            :: "r"(sa), "l"(src), "r"(sa + 16u), "l"(src + 4));
        asm volatile("cp.async.commit_group;");
    }
    asm volatile("cp.async.wait_group %0;" :: "n"(DPF - 2));
    __syncwarp();

    float2 kA[4], kB[4], qA[4], qB[4];
    float vA, aA, vB, aB;
    {
        const float* p = buf;
        float4 kv0 = *reinterpret_cast<const float4*>(p + c * 8);
        float4 kv1 = *reinterpret_cast<const float4*>(p + c * 8 + 4);
        kA[0] = make_float2(kv0.x, kv0.y); kA[1] = make_float2(kv0.z, kv0.w);
        kA[2] = make_float2(kv1.x, kv1.y); kA[3] = make_float2(kv1.z, kv1.w);
        vA = p[128 + i];
        aA = p[192 + i];
    }
    #pragma unroll
    for (int m = 0; m < 4; m++) { qA[m] = make_float2(0.f, 0.f); }

    float r;
    {
        float2 ra = f2mul(s[0], kA[0]);
        float2 rb = f2mul(s[1], kA[1]);
        ra = f2fma(s[2], kA[2], ra);
        rb = f2fma(s[3], kA[3], rb);
        ra = f2add(ra, rb);
        r = ra.x + ra.y;
        r += __shfl_xor_sync(0xffffffffu, r, 1);
        r += __shfl_xor_sync(0xffffffffu, r, 2);
        r += __shfl_xor_sync(0xffffffffu, r, 4);
    }

    // main loop: 16-step groups; poll flags covering compute + prefetch window
    for (int t0 = 0; t0 < T_STEPS; t0 += 16) {
        const int mb = t0 >> 4;
        wait_flag(mb);
        wait_flag(mb + 1);
        #pragma unroll 1
        for (int u = 0; u < 8; u++) {
            const int t = t0 + u * 2;
            scan_step(ctx, t,     s, kA, kB, qA, qB, vA, aA, vB, aB, r, buf);
            scan_step(ctx, t + 1, s, kB, kA, qB, qA, vB, aB, vA, aA, r, buf);
        }
    }

    // out_{T-1} = s_T . q_{T-1} (bank qA)
    {
        float2 oa = f2mul(s[0], qA[0]);
        float2 ob = f2mul(s[1], qA[1]);
        oa = f2fma(s[2], qA[2], oa);
        ob = f2fma(s[3], qA[3], ob);
        oa = f2add(oa, ob);
        float oq = oa.x + oa.y;
        oq += __shfl_xor_sync(0xffffffffu, oq, 1);
        oq += __shfl_xor_sync(0xffffffffu, oq, 2);
        oq += __shfl_xor_sync(0xffffffffu, oq, 4);
        if (c == 0)
            out[((size_t)(T_STEPS - 1) * BATCH + b) * NST + i] = oq;
    }

    float* fp = &Sfin[(size_t)(b * NST + i) * NST + c * 8];
    reinterpret_cast<float4*>(fp)[0] = make_float4(s[0].x, s[0].y, s[1].x, s[1].y);
    reinterpret_cast<float4*>(fp)[1] = make_float4(s[2].x, s[2].y, s[3].x, s[3].y);
}

// ============================================================================
// fused kernel: bids [0,128) scan, [128, 128+512) proj
// ============================================================================
__global__ void __launch_bounds__(128, 4) fused_kernel(
    const float* __restrict__ x,
    const float* __restrict__ S0,
    const float* __restrict__ Wk, const float* __restrict__ Wv,
    const float* __restrict__ Wq, const float* __restrict__ Wa,
    const float* __restrict__ b_alpha,
    const float* __restrict__ d_g,
    const float* __restrict__ b_g,
    float* __restrict__ out,
    float* __restrict__ Sfin)
{
    __shared__ __align__(16) float smem[PROJ_SMEM_FLOATS];

    const int bid = blockIdx.x;
    if (bid < SCAN_CTAS) {
        if (threadIdx.x >= 32) return;   // scan uses one warp
        scan_role(smem, bid, S0, d_g, b_g, out, Sfin);
    } else {
        proj_role(smem, bid - SCAN_CTAS, x, Wk, Wq, Wv, Wa, b_alpha);
    }
}

// ============================================================================
// flag reset (each graph replay) and output self-gate
// ============================================================================
__global__ void zero_flags_kernel() {
    g_flags[threadIdx.x] = 0;
}

__global__ void __launch_bounds__(256) gate_kernel(float* __restrict__ out)
{
    int idx = blockIdx.x * 1024 + threadIdx.x * 4;
    float4 v = *reinterpret_cast<float4*>(&out[idx]);
    v.x = v.x * v.x * sigmoidf_fast(v.x);
    v.y = v.y * v.y * sigmoidf_fast(v.y);
    v.z = v.z * v.z * sigmoidf_fast(v.z);
    v.w = v.w * v.w * sigmoidf_fast(v.w);
    *reinterpret_cast<float4*>(&out[idx]) = v;
}

// ============================================================================
extern "C" void kernel_launch(void* const* d_in, const int* in_sizes, int n_in,
                              void* d_out, int out_size) {
    const float* x   = (const float*)d_in[0];
    const float* S0  = (const float*)d_in[1];
    const float* Wk  = (const float*)d_in[2];
    const float* Wv  = (const float*)d_in[3];
    const float* Wq  = (const float*)d_in[4];
    const float* Wa  = (const float*)d_in[5];
    const float* ba  = (const float*)d_in[6];
    const float* dg  = (const float*)d_in[7];
    const float* bg  = (const float*)d_in[8];

    float* out  = (float*)d_out;                         // [T,B,N]
    float* Sfin = out + (size_t)T_STEPS * BATCH * NST;   // [B,N,N]

    zero_flags_kernel<<<1, NMB>>>();
    fused_kernel<<<SCAN_CTAS + PROJ_CTAS, 128>>>(
        x, S0, Wk, Wv, Wq, Wa, ba, dg, bg, out, Sfin);
    gate_kernel<<<(T_STEPS * BATCH * NST) / 1024, 256>>>(out);
}

// round 8
// speedup vs baseline: 1.1511x; 1.1511x over previous
#include <cuda_runtime.h>
#include <cstdint>
#include <cstring>

#define T_STEPS 2048
#define BATCH   8
#define DIMK    1024
#define NST     64
#define M_ROWS  (T_STEPS * BATCH)
#define NCOL    256

// 16 MB scratch: projections, layout [t*BATCH+b][ k(0:64) | q(64:128) | v(128:192) | alpha(192:256) ]
__device__ __align__(16) float g_proj[(size_t)M_ROWS * NCOL];

union F2U { float2 f2; unsigned long long u; };

__device__ __forceinline__ float2 f2fma(float2 a, float2 b, float2 c) {
    F2U ua, ub, uc, ud; ua.f2 = a; ub.f2 = b; uc.f2 = c;
    asm("fma.rn.f32x2 %0, %1, %2, %3;" : "=l"(ud.u) : "l"(ua.u), "l"(ub.u), "l"(uc.u));
    return ud.f2;
}
__device__ __forceinline__ float2 f2mul(float2 a, float2 b) {
    F2U ua, ub, ud; ua.f2 = a; ub.f2 = b;
    asm("mul.rn.f32x2 %0, %1, %2;" : "=l"(ud.u) : "l"(ua.u), "l"(ub.u));
    return ud.f2;
}
__device__ __forceinline__ float2 f2add(float2 a, float2 b) {
    F2U ua, ub, ud; ua.f2 = a; ub.f2 = b;
    asm("add.rn.f32x2 %0, %1, %2;" : "=l"(ud.u) : "l"(ua.u), "l"(ub.u));
    return ud.f2;
}
__device__ __forceinline__ float2 f2dup(float a) {
    F2U ud;
    asm("mov.b64 %0, {%1, %1};" : "=l"(ud.u) : "f"(a));
    return ud.f2;
}
__device__ __forceinline__ float sigmoidf_fast(float x) {
    return __fdividef(1.0f, 1.0f + __expf(-x));
}

// ============================================================================
// tf32 helpers
// ============================================================================
__device__ __forceinline__ uint32_t f2tf(float a) {
    uint32_t r;
    asm("cvt.rna.tf32.f32 %0, %1;" : "=r"(r) : "f"(a));
    return r;
}
// hi/lo split: a = hi + lo (hi, lo both tf32); lo = tf32(a - hi)
__device__ __forceinline__ void tf_split(float a, uint32_t& hi, uint32_t& lo) {
    hi = f2tf(a);
    lo = f2tf(__fsub_rn(a, __uint_as_float(hi)));
}
__device__ __forceinline__ void mma_tf32(float (&d)[4], const uint32_t (&a)[4],
                                         const uint32_t (&b)[2]) {
    asm("mma.sync.aligned.m16n8k8.row.col.f32.tf32.tf32.f32 "
        "{%0,%1,%2,%3},{%4,%5,%6,%7},{%8,%9},{%0,%1,%2,%3};"
        : "+f"(d[0]), "+f"(d[1]), "+f"(d[2]), "+f"(d[3])
        : "r"(a[0]), "r"(a[1]), "r"(a[2]), "r"(a[3]), "r"(b[0]), "r"(b[1]));
}

// ============================================================================
// Kernel 1: projection GEMM on tensor cores, 3xTF32.
// C[m][n] = sum_d x[m][d] * W_sel[n][d]; blockIdx.y selects weight matrix.
// CTA: 256 thr (8 warps), tile 128m x 64n x 32k. Warp: 32m x 32n.
// mma m16n8k8 row.col: A = x (row-major m x k), B = W (col-major k x n, which
// is exactly W[n][k] row-major). hi/lo conversion at fragment load.
// ============================================================================
#define TBM 128
#define TBN 64
#define TBK 32
#define XS_STRIDE 36
#define WS_STRIDE 36

__global__ void __launch_bounds__(256, 2) proj_tc_kernel(
    const float* __restrict__ x,
    const float* __restrict__ Wk, const float* __restrict__ Wq,
    const float* __restrict__ Wv, const float* __restrict__ Wa,
    const float* __restrict__ b_alpha)
{
    __shared__ __align__(16) float Xs[TBM * XS_STRIDE];   // [m][k]
    __shared__ __align__(16) float Ws[TBN * WS_STRIDE];   // [n][k]

    const int tid = threadIdx.x;
    const int m0  = blockIdx.x * TBM;
    const int sel = blockIdx.y;
    const float* W = (sel == 0) ? Wk : (sel == 1) ? Wq : (sel == 2) ? Wv : Wa;

    const int warp  = tid >> 5;
    const int lane  = tid & 31;
    const int g     = lane >> 2;       // group 0..7
    const int tg    = lane & 3;        // thread-in-group 0..3
    const int wm    = warp >> 1;       // 0..3  (32 m-rows each)
    const int wn    = warp & 1;        // 0..1  (32 n-cols each)
    const int am0   = wm * 32 + g;     // A fragment base row (within tile)
    const int cn0   = wn * 32 + g;     // B/C fragment base col (within tile)

    // staging loader indices: 8 float4 per row-chunk; row = tid/8 + 32*i
    const int lr0 = tid >> 3;          // 0..31
    const int lc0 = (tid & 7) * 4;     // 0,4,...,28

    const float* xp = &x[(size_t)(m0 + lr0) * DIMK + lc0];
    const float* wp = &W[(size_t)lr0 * DIMK + lc0];

    float acc[2][4][4];   // [mt][nt][c0..c3]
    #pragma unroll
    for (int mt = 0; mt < 2; mt++)
        #pragma unroll
        for (int nt = 0; nt < 4; nt++)
            #pragma unroll
            for (int j = 0; j < 4; j++) acc[mt][nt][j] = 0.f;

    // register prefetch of first K-tile
    float4 xr[4], wr[2];
    #pragma unroll
    for (int i = 0; i < 4; i++)
        xr[i] = *reinterpret_cast<const float4*>(xp + (size_t)i * 32 * DIMK);
    #pragma unroll
    for (int i = 0; i < 2; i++)
        wr[i] = *reinterpret_cast<const float4*>(wp + (size_t)i * 32 * DIMK);

    for (int k0 = 0; k0 < DIMK; k0 += TBK) {
        __syncthreads();
        #pragma unroll
        for (int i = 0; i < 4; i++)
            *reinterpret_cast<float4*>(&Xs[(lr0 + 32 * i) * XS_STRIDE + lc0]) = xr[i];
        #pragma unroll
        for (int i = 0; i < 2; i++)
            *reinterpret_cast<float4*>(&Ws[(lr0 + 32 * i) * WS_STRIDE + lc0]) = wr[i];
        __syncthreads();

        if (k0 + TBK < DIMK) {
            #pragma unroll
            for (int i = 0; i < 4; i++)
                xr[i] = *reinterpret_cast<const float4*>(xp + (size_t)i * 32 * DIMK + k0 + TBK);
            #pragma unroll
            for (int i = 0; i < 2; i++)
                wr[i] = *reinterpret_cast<const float4*>(wp + (size_t)i * 32 * DIMK + k0 + TBK);
        }

        #pragma unroll
        for (int ks = 0; ks < TBK / 8; ks++) {
            const int kk = ks * 8;

            // A fragments (2 m-tiles), hi/lo
            uint32_t ah[2][4], al[2][4];
            #pragma unroll
            for (int mt = 0; mt < 2; mt++) {
                const int r0 = (am0 + mt * 16) * XS_STRIDE;
                const int r8 = (am0 + mt * 16 + 8) * XS_STRIDE;
                float a0 = Xs[r0 + kk + tg];
                float a1 = Xs[r8 + kk + tg];
                float a2 = Xs[r0 + kk + tg + 4];
                float a3 = Xs[r8 + kk + tg + 4];
                tf_split(a0, ah[mt][0], al[mt][0]);
                tf_split(a1, ah[mt][1], al[mt][1]);
                tf_split(a2, ah[mt][2], al[mt][2]);
                tf_split(a3, ah[mt][3], al[mt][3]);
            }
            // B fragments (4 n-tiles), hi/lo
            uint32_t bh[4][2], bl[4][2];
            #pragma unroll
            for (int nt = 0; nt < 4; nt++) {
                const int c0 = (cn0 + nt * 8) * WS_STRIDE;
                float b0 = Ws[c0 + kk + tg];
                float b1 = Ws[c0 + kk + tg + 4];
                tf_split(b0, bh[nt][0], bl[nt][0]);
                tf_split(b1, bh[nt][1], bl[nt][1]);
            }
            // 3xTF32: D += Ah*Bh + Al*Bh + Ah*Bl
            #pragma unroll
            for (int mt = 0; mt < 2; mt++)
                #pragma unroll
                for (int nt = 0; nt < 4; nt++) {
                    mma_tf32(acc[mt][nt], ah[mt], bh[nt]);
                    mma_tf32(acc[mt][nt], al[mt], bh[nt]);
                    mma_tf32(acc[mt][nt], ah[mt], bl[nt]);
                }
        }
    }

    // epilogue: C fragment c0=C[g][2tg], c1=C[g][2tg+1], c2=C[g+8][2tg], c3=C[g+8][2tg+1]
    #pragma unroll
    for (int mt = 0; mt < 2; mt++) {
        #pragma unroll
        for (int nt = 0; nt < 4; nt++) {
            const int row = m0 + wm * 32 + mt * 16 + g;
            const int col = wn * 32 + nt * 8 + 2 * tg;   // within 64-wide matrix
            float c0 = acc[mt][nt][0], c1 = acc[mt][nt][1];
            float c2 = acc[mt][nt][2], c3 = acc[mt][nt][3];
            if (sel == 3) {
                const float ba0 = b_alpha[col], ba1 = b_alpha[col + 1];
                c0 = sigmoidf_fast(c0 + ba0); c1 = sigmoidf_fast(c1 + ba1);
                c2 = sigmoidf_fast(c2 + ba0); c3 = sigmoidf_fast(c3 + ba1);
            }
            *reinterpret_cast<float2*>(&g_proj[(size_t)row * NCOL + sel * 64 + col])
                = make_float2(c0, c1);
            *reinterpret_cast<float2*>(&g_proj[(size_t)(row + 8) * NCOL + sel * 64 + col])
                = make_float2(c2, c3);
        }
    }
}

// ============================================================================
// Kernel 2: sequential scan with decoupled retrieved-value recurrence (R6).
//   r_{t+1} = alpha_t*(s_t . k_{t+1}) + beta_t*(k_t . k_{t+1})
// 128 blocks x 32 threads; 4 rows/warp, 8 lanes/row. Unrolled x2, swapped banks.
// ============================================================================
#define DPF 8   // ring slots

struct ScanCtx {
    const float* gp_base;
    float* out;
    uint32_t sbase;
    int b, i, c, loff;
    float dgl, bgl;
};

__device__ __forceinline__ void scan_step(
    const ScanCtx& ctx, int t,
    float2 (&s)[4],
    float2 (&kc)[4], float2 (&kn)[4],
    float2 (&qp)[4], float2 (&qc)[4],
    float v_c, float a_c,
    float& v_n, float& a_n,
    float& r,
    float (&buf)[DPF][NCOL])
{
    {
        int tf = t + DPF - 1;
        if (tf > T_STEPS - 1) tf = T_STEPS - 1;
        int slot = tf & (DPF - 1);
        const float* src = ctx.gp_base + (size_t)tf * BATCH * NCOL + ctx.loff;
        uint32_t sa = ctx.sbase + (uint32_t)(slot * NCOL + ctx.loff) * 4u;
        asm volatile(
            "cp.async.ca.shared.global [%0], [%1], 16;\n\t"
            "cp.async.ca.shared.global [%2], [%3], 16;\n\t"
            :: "r"(sa), "l"(src), "r"(sa + 16u), "l"(src + 4));
        asm volatile("cp.async.commit_group;");
    }
    asm volatile("cp.async.wait_group %0;" :: "n"(DPF - 2));
    __syncwarp();

    const int tn = (t + 1 < T_STEPS) ? (t + 1) : t;
    const float* pn = &buf[tn & (DPF - 1)][0];
    const float* pc = &buf[t & (DPF - 1)][0];
    {
        float4 kv0 = *reinterpret_cast<const float4*>(pn + ctx.c * 8);
        float4 kv1 = *reinterpret_cast<const float4*>(pn + ctx.c * 8 + 4);
        kn[0] = make_float2(kv0.x, kv0.y); kn[1] = make_float2(kv0.z, kv0.w);
        kn[2] = make_float2(kv1.x, kv1.y); kn[3] = make_float2(kv1.z, kv1.w);
        float4 qv0 = *reinterpret_cast<const float4*>(pc + 64 + ctx.c * 8);
        float4 qv1 = *reinterpret_cast<const float4*>(pc + 64 + ctx.c * 8 + 4);
        qc[0] = make_float2(qv0.x, qv0.y); qc[1] = make_float2(qv0.z, qv0.w);
        qc[2] = make_float2(qv1.x, qv1.y); qc[3] = make_float2(qv1.z, qv1.w);
        v_n = pn[128 + ctx.i];
        a_n = pn[192 + ctx.i];
    }

    float2 xa = f2mul(s[0], kn[0]);
    float2 xb = f2mul(s[1], kn[1]);
    float2 oa = f2mul(s[0], qp[0]);
    float2 ob = f2mul(s[1], qp[1]);
    float2 da = f2mul(kc[0], kn[0]);
    float2 db = f2mul(kc[1], kn[1]);
    xa = f2fma(s[2], kn[2], xa);
    xb = f2fma(s[3], kn[3], xb);
    oa = f2fma(s[2], qp[2], oa);
    ob = f2fma(s[3], qp[3], ob);
    da = f2fma(kc[2], kn[2], da);
    db = f2fma(kc[3], kn[3], db);
    xa = f2add(xa, xb);
    oa = f2add(oa, ob);
    da = f2add(da, db);
    float a1 = xa.x + xa.y;
    float oq = oa.x + oa.y;
    float d2 = da.x + da.y;

    a1 += __shfl_xor_sync(0xffffffffu, a1, 1);
    oq += __shfl_xor_sync(0xffffffffu, oq, 1);
    d2 += __shfl_xor_sync(0xffffffffu, d2, 1);
    a1 += __shfl_xor_sync(0xffffffffu, a1, 2);
    oq += __shfl_xor_sync(0xffffffffu, oq, 2);
    d2 += __shfl_xor_sync(0xffffffffu, d2, 2);
    a1 += __shfl_xor_sync(0xffffffffu, a1, 4);
    oq += __shfl_xor_sync(0xffffffffu, oq, 4);
    d2 += __shfl_xor_sync(0xffffffffu, d2, 4);

    float e;
    asm("ex2.approx.f32 %0, %1;" : "=f"(e) : "f"(__fmaf_rn(ctx.dgl, r, ctx.bgl)));
    float gt;
    asm("rcp.approx.f32 %0, %1;" : "=f"(gt) : "f"(1.0f + e));
    const float beta = (1.0f - a_c) * v_c * gt;

    const float2 av = f2dup(a_c);
    const float2 bv = f2dup(beta);
    #pragma unroll
    for (int m = 0; m < 4; m++)
        s[m] = f2fma(av, s[m], f2mul(bv, kc[m]));

    r = __fmaf_rn(a_c, a1, beta * d2);

    if (t > 0 && ctx.c == 0)
        ctx.out[((size_t)(t - 1) * BATCH + ctx.b) * NST + ctx.i] = oq;
}

__global__ void __launch_bounds__(32) scan_kernel(
    const float* __restrict__ S0,
    const float* __restrict__ d_g,
    const float* __restrict__ b_g,
    float* __restrict__ out,     // [T,B,N] raw
    float* __restrict__ Sfin)    // [B,N,N]
{
    __shared__ __align__(16) float buf[DPF][NCOL];

    const int bx   = blockIdx.x;
    const int b    = bx >> 4;
    const int rg   = bx & 15;
    const int lane = threadIdx.x;
    const int r_   = lane >> 3;
    const int c    = lane & 7;
    const int i    = rg * 4 + r_;

    const float L2E = 1.4426950408889634f;

    ScanCtx ctx;
    ctx.gp_base = &g_proj[(size_t)b * NCOL];
    ctx.out  = out;
    ctx.b = b; ctx.i = i; ctx.c = c;
    ctx.loff = lane * 8;
    ctx.dgl = -d_g[i] * L2E;
    ctx.bgl = -b_g[i] * L2E;
    ctx.sbase = (uint32_t)__cvta_generic_to_shared(&buf[0][0]);

    float2 s[4];
    {
        const float4* sp = reinterpret_cast<const float4*>(&S0[(size_t)(b * NST + i) * NST + c * 8]);
        float4 v0 = sp[0], v1 = sp[1];
        s[0] = make_float2(v0.x, v0.y); s[1] = make_float2(v0.z, v0.w);
        s[2] = make_float2(v1.x, v1.y); s[3] = make_float2(v1.z, v1.w);
    }

    #pragma unroll
    for (int d = 0; d < DPF - 1; d++) {
        const float* src = ctx.gp_base + (size_t)d * BATCH * NCOL + ctx.loff;
        uint32_t sa = ctx.sbase + (uint32_t)(d * NCOL + ctx.loff) * 4u;
        asm volatile(
            "cp.async.ca.shared.global [%0], [%1], 16;\n\t"
            "cp.async.ca.shared.global [%2], [%3], 16;\n\t"
            :: "r"(sa), "l"(src), "r"(sa + 16u), "l"(src + 4));
        asm volatile("cp.async.commit_group;");
    }
    asm volatile("cp.async.wait_group %0;" :: "n"(DPF - 2));
    __syncwarp();

    float2 kA[4], kB[4], qA[4], qB[4];
    float vA, aA, vB, aB;
    {
        const float* p = &buf[0][0];
        float4 kv0 = *reinterpret_cast<const float4*>(p + c * 8);
        float4 kv1 = *reinterpret_cast<const float4*>(p + c * 8 + 4);
        kA[0] = make_float2(kv0.x, kv0.y); kA[1] = make_float2(kv0.z, kv0.w);
        kA[2] = make_float2(kv1.x, kv1.y); kA[3] = make_float2(kv1.z, kv1.w);
        vA = p[128 + i];
        aA = p[192 + i];
    }
    #pragma unroll
    for (int m = 0; m < 4; m++) { qA[m] = make_float2(0.f, 0.f); }

    float r;
    {
        float2 ra = f2mul(s[0], kA[0]);
        float2 rb = f2mul(s[1], kA[1]);
        ra = f2fma(s[2], kA[2], ra);
        rb = f2fma(s[3], kA[3], rb);
        ra = f2add(ra, rb);
        r = ra.x + ra.y;
        r += __shfl_xor_sync(0xffffffffu, r, 1);
        r += __shfl_xor_sync(0xffffffffu, r, 2);
        r += __shfl_xor_sync(0xffffffffu, r, 4);
    }

    for (int t = 0; t < T_STEPS; t += 2) {
        scan_step(ctx, t,     s, kA, kB, qA, qB, vA, aA, vB, aB, r, buf);
        scan_step(ctx, t + 1, s, kB, kA, qB, qA, vB, aB, vA, aA, r, buf);
    }

    {
        float2 oa = f2mul(s[0], qA[0]);
        float2 ob = f2mul(s[1], qA[1]);
        oa = f2fma(s[2], qA[2], oa);
        ob = f2fma(s[3], qA[3], ob);
        oa = f2add(oa, ob);
        float oq = oa.x + oa.y;
        oq += __shfl_xor_sync(0xffffffffu, oq, 1);
        oq += __shfl_xor_sync(0xffffffffu, oq, 2);
        oq += __shfl_xor_sync(0xffffffffu, oq, 4);
        if (c == 0)
            out[((size_t)(T_STEPS - 1) * BATCH + b) * NST + i] = oq;
    }

    float* fp = &Sfin[(size_t)(b * NST + i) * NST + c * 8];
    reinterpret_cast<float4*>(fp)[0] = make_float4(s[0].x, s[0].y, s[1].x, s[1].y);
    reinterpret_cast<float4*>(fp)[1] = make_float4(s[2].x, s[2].y, s[3].x, s[3].y);
}

// ============================================================================
// Kernel 3: apply self-gate y = x * silu(x) = x^2 * sigmoid(x) over out[T,B,N]
// ============================================================================
__global__ void __launch_bounds__(256) gate_kernel(float* __restrict__ out)
{
    int idx = blockIdx.x * 1024 + threadIdx.x * 4;
    float4 v = *reinterpret_cast<float4*>(&out[idx]);
    v.x = v.x * v.x * sigmoidf_fast(v.x);
    v.y = v.y * v.y * sigmoidf_fast(v.y);
    v.z = v.z * v.z * sigmoidf_fast(v.z);
    v.w = v.w * v.w * sigmoidf_fast(v.w);
    *reinterpret_cast<float4*>(&out[idx]) = v;
}

// ============================================================================
extern "C" void kernel_launch(void* const* d_in, const int* in_sizes, int n_in,
                              void* d_out, int out_size) {
    const float* x   = (const float*)d_in[0];
    const float* S0  = (const float*)d_in[1];
    const float* Wk  = (const float*)d_in[2];
    const float* Wv  = (const float*)d_in[3];
    const float* Wq  = (const float*)d_in[4];
    const float* Wa  = (const float*)d_in[5];
    const float* ba  = (const float*)d_in[6];
    const float* dg  = (const float*)d_in[7];
    const float* bg  = (const float*)d_in[8];

    float* out  = (float*)d_out;                         // [T,B,N]
    float* Sfin = out + (size_t)T_STEPS * BATCH * NST;   // [B,N,N]

    dim3 g1(M_ROWS / TBM, 4);
    proj_tc_kernel<<<g1, 256>>>(x, Wk, Wq, Wv, Wa, ba);
    scan_kernel<<<128, 32>>>(S0, dg, bg, out, Sfin);
    gate_kernel<<<(T_STEPS * BATCH * NST) / 1024, 256>>>(out);
}